// round 15
// baseline (speedup 1.0000x reference)
#include <cuda_runtime.h>
#include <cuda_bf16.h>
#include <math.h>

// Problem constants
#define ROWS   49152      // B*T*N = 8*12*512
#define DCH    128        // D
#define NNODES 512        // N
#define NBT    96         // B*T
#define NH     4          // heads (d)
#define MBLK   384        // ROWS / 128

// attention smem strides (units: 4B words)
#define KT2PAD 1032       // Ktp row stride: [16][1032], conflict-free LDS.64
#define VPPAD  72         // Vh/Vl row stride: [128][72], conflict-free LDS.64
#define AQPAD  36         // Asq row stride, [256][36]

// GEMM smem pads (bf16-pair words)
#define APAD 20           // A row stride in words (16 used)
#define BPAD 136          // B kpair stride in words
// double-buffer layout (words): AsH | AsL | BsH | BsL per buffer
#define GA   (128 * APAD)             // 2560
#define GB   (16 * BPAD)              // 2176
#define GBUF (2 * GA + 2 * GB)        // 9472 words per buffer
#define GEMM_SMEM (2 * GBUF * 4)      // 75776 bytes

// pre-split W regions (pairword granularity)
#define WOFF_O 49152      // q:0, k:16384, v:32768, o:49152
#define WTOTAL 57344      // 3*16384 + 64*128

// ---------------- scratch (device globals; no cudaMalloc allowed) ----------
__device__ float    g_qraw[ROWS * DCH];
__device__ float    g_kraw[ROWS * DCH];
__device__ float    g_vraw[ROWS * DCH];
__device__ float    g_aout[ROWS * DCH];
__device__ float    g_oraw[ROWS * DCH];
__device__ unsigned g_mask[NNODES * 16];      // A>0 bitmap: row n, 16 words
__device__ unsigned g_WH[WTOTAL], g_WL[WTOTAL]; // pre-split packed bf16 weights
// deterministic BN partials, layout [z][ch][block]: slot=(z*128+ch)*384+b
__device__ float g_psum[4 * DCH * MBLK];
__device__ float g_psumsq[4 * DCH * MBLK];
__device__ float g_scale[4 * DCH];
__device__ float g_shift[4 * DCH];

// ---------------- helpers ----------------------------------------------------
__device__ __forceinline__ unsigned f2tf32(float f) {
    unsigned r;
    asm("cvt.rna.tf32.f32 %0, %1;" : "=r"(r) : "f"(f));
    return r;
}

__device__ __forceinline__ unsigned bf16x2pk(float hi, float lo) {
    unsigned r;
    asm("cvt.rn.bf16x2.f32 %0, %1, %2;" : "=r"(r) : "f"(hi), "f"(lo));
    return r;   // low 16 bits = bf16(lo), high = bf16(hi)
}

__device__ __forceinline__ float ex2f(float x) {
    float r;
    asm("ex2.approx.f32 %0, %1;" : "=f"(r) : "f"(x));
    return r;
}

// split packed pair (p0 even, p1 odd) into hi/lo packed words
__device__ __forceinline__ void packsplit(float p0, float p1,
                                          unsigned& hi, unsigned& lo) {
    hi = bf16x2pk(p1, p0);
    float f0 = __uint_as_float(hi << 16);
    float f1 = __uint_as_float(hi & 0xffff0000u);
    lo = bf16x2pk(p1 - f1, p0 - f0);
}

__device__ __forceinline__ void mma_tf32(float* c, const unsigned* a, const unsigned* b) {
    asm volatile(
        "mma.sync.aligned.m16n8k8.row.col.f32.tf32.tf32.f32 "
        "{%0,%1,%2,%3}, {%4,%5,%6,%7}, {%8,%9}, {%0,%1,%2,%3};\n"
        : "+f"(c[0]), "+f"(c[1]), "+f"(c[2]), "+f"(c[3])
        : "r"(a[0]), "r"(a[1]), "r"(a[2]), "r"(a[3]), "r"(b[0]), "r"(b[1]));
}

__device__ __forceinline__ void mma_bf16(float* c, const unsigned* a, const unsigned* b) {
    asm volatile(
        "mma.sync.aligned.m16n8k16.row.col.f32.bf16.bf16.f32 "
        "{%0,%1,%2,%3}, {%4,%5,%6,%7}, {%8,%9}, {%0,%1,%2,%3};\n"
        : "+f"(c[0]), "+f"(c[1]), "+f"(c[2]), "+f"(c[3])
        : "r"(a[0]), "r"(a[1]), "r"(a[2]), "r"(a[3]), "r"(b[0]), "r"(b[1]));
}

__device__ __forceinline__ void split_bf16(float v, unsigned short& h, unsigned short& l) {
    __nv_bfloat16 hb = __float2bfloat16_rn(v);
    float hf = __bfloat162float(hb);
    __nv_bfloat16 lb = __float2bfloat16_rn(v - hf);
    h = *(unsigned short*)&hb;
    l = *(unsigned short*)&lb;
}

__device__ __forceinline__ unsigned pack2(unsigned short lo, unsigned short hi) {
    return (unsigned)lo | ((unsigned)hi << 16);   // low 16 = even-k element
}

// ---------------- setup: adjacency bitmap + weight pre-split (merged) -------
__global__ void setup_kernel(const float* __restrict__ A,
                             const float* __restrict__ Wq,
                             const float* __restrict__ Wk,
                             const float* __restrict__ Wv,
                             const float* __restrict__ Wo)
{
    if (blockIdx.x < 16) {
        int row  = (blockIdx.x * 1024 + threadIdx.x) >> 5;
        int lane = threadIdx.x & 31;
        for (int w = 0; w < 16; w++) {
            float a = A[row * NNODES + w * 32 + lane];
            unsigned bal = __ballot_sync(0xffffffffu, a > 0.f);
            if (lane == 0) g_mask[row * 16 + w] = bal;
        }
    } else {
        int idx = (blockIdx.x - 16) * 1024 + threadIdx.x;
        if (idx >= WTOTAL) return;
        const float* W;
        int off;
        if (idx < 16384)      { W = Wq; off = 0; }
        else if (idx < 32768) { W = Wk; off = 16384; }
        else if (idx < 49152) { W = Wv; off = 32768; }
        else                  { W = Wo; off = WOFF_O; }
        int local = idx - off;
        int kp = local >> 7, n = local & 127;
        float v0 = W[(size_t)(2 * kp) * 128 + n];
        float v1 = W[(size_t)(2 * kp + 1) * 128 + n];
        unsigned short h0, l0, h1, l1;
        split_bf16(v0, h0, l0);
        split_bf16(v1, h1, l1);
        g_WH[idx] = pack2(h0, h1);
        g_WL[idx] = pack2(l0, l1);
    }
}

// stage one 128x32 A tile (split) + 16x128 B pairword tile into buffer bufs
__device__ __forceinline__ void gemm_stage(
    unsigned* AsH, unsigned* AsL, unsigned* BsH, unsigned* BsL,
    const float* __restrict__ Abase, int kofs,
    const unsigned* __restrict__ WH, const unsigned* __restrict__ WL,
    int kp0, int tid, int row0)
{
    // B tile: pure copy of pre-split pairwords
#pragma unroll
    for (int t = 0; t < 2; t++) {
        int i  = tid + 256 * t;
        int kp = i >> 5;
        int n4 = (i & 31) << 2;
        uint4 hv = *(const uint4*)&WH[(size_t)(kp0 + kp) * 128 + n4];
        uint4 lv = *(const uint4*)&WL[(size_t)(kp0 + kp) * 128 + n4];
        *(uint4*)&BsH[kp * BPAD + n4] = hv;
        *(uint4*)&BsL[kp * BPAD + n4] = lv;
    }
    // A tile: load + split
#pragma unroll
    for (int t = 0; t < 4; t++) {
        int i  = tid + 256 * t;
        int r  = i >> 3;
        int kq = (i & 7) << 2;
        float4 v = *(const float4*)(Abase + (size_t)(row0 + r) * 128 + kofs + kq);
        unsigned short hx, lx, hy, ly, hz, lz, hw, lw;
        split_bf16(v.x, hx, lx); split_bf16(v.y, hy, ly);
        split_bf16(v.z, hz, lz); split_bf16(v.w, hw, lw);
        int o = r * APAD + (kq >> 1);
        AsH[o + 0] = pack2(hx, hy);  AsH[o + 1] = pack2(hz, hw);
        AsL[o + 0] = pack2(lx, ly);  AsL[o + 1] = pack2(lz, lw);
    }
}

// ---------------- split-bf16 tensor GEMM, 128x128 tile, BK=32, 2-buf --------
// Y = A @ W via AhBh + AlBh + AhBl (~fp32 accuracy). Double-buffered smem:
// stage(k+1) overlaps mma(k); one __syncthreads per k-iteration.
// Fused BN partials in [z][ch][block] layout.
template <int KDIM, bool CAT>
__global__ __launch_bounds__(256)
void mma_gemm_kernel(const float* __restrict__ A0, const float* __restrict__ A1,
                     int wbase, int wstep,
                     float* __restrict__ Y0, float* __restrict__ Y1,
                     float* __restrict__ Y2, int zbase)
{
    extern __shared__ __align__(16) unsigned gsm[];
    __shared__ float ssum[2][128], ssq[2][128];

    const int z = blockIdx.z;
    float* Y = (z == 0) ? Y0 : (z == 1) ? Y1 : Y2;
    const unsigned* WH = g_WH + wbase + z * wstep;
    const unsigned* WL = g_WL + wbase + z * wstep;

    const int tid  = threadIdx.x;
    const int lane = tid & 31;
    const int wid  = tid >> 5;
    const int wm   = wid >> 2;
    const int wn   = wid & 3;
    const int row0 = blockIdx.x * 128;
    const int g    = lane >> 2;
    const int tg   = lane & 3;
    const int NK   = KDIM / 32;

    unsigned* bufAsH[2] = {gsm,             gsm + GBUF};
    unsigned* bufAsL[2] = {gsm + GA,        gsm + GBUF + GA};
    unsigned* bufBsH[2] = {gsm + 2 * GA,    gsm + GBUF + 2 * GA};
    unsigned* bufBsL[2] = {gsm + 2 * GA + GB, gsm + GBUF + 2 * GA + GB};

    float acc[4][4][4];
#pragma unroll
    for (int mt = 0; mt < 4; mt++)
#pragma unroll
        for (int nt = 0; nt < 4; nt++)
#pragma unroll
            for (int q = 0; q < 4; q++) acc[mt][nt][q] = 0.f;

    // prologue: stage tile 0
    {
        const float* Abase = A0; int kofs = 0;
        gemm_stage(bufAsH[0], bufAsL[0], bufBsH[0], bufBsL[0],
                   Abase, kofs, WH, WL, 0, tid, row0);
    }
    __syncthreads();

    int p = 0;
    for (int ki = 0; ki < NK; ki++) {
        // stage next tile into the other buffer (overlaps with mma below)
        if (ki + 1 < NK) {
            int k0n = (ki + 1) * 32;
            const float* Abase; int kofs;
            if (CAT) {
                if (k0n < 128) { Abase = A0; kofs = k0n; }
                else           { Abase = A1; kofs = k0n - 128; }
            } else { Abase = A0; kofs = k0n; }
            gemm_stage(bufAsH[p ^ 1], bufAsL[p ^ 1], bufBsH[p ^ 1], bufBsL[p ^ 1],
                       Abase, kofs, WH, WL, k0n >> 1, tid, row0);
        }

        // compute on buffer p
        unsigned* AsH = bufAsH[p];
        unsigned* AsL = bufAsL[p];
        unsigned* BsH = bufBsH[p];
        unsigned* BsL = bufBsL[p];
#pragma unroll
        for (int s = 0; s < 2; s++) {
            const int kb = s * 8;
            unsigned afH[4][4], afL[4][4];
#pragma unroll
            for (int mt = 0; mt < 4; mt++) {
                int rB = wm * 64 + mt * 16;
                afH[mt][0] = AsH[(rB + g) * APAD + kb + tg];
                afH[mt][1] = AsH[(rB + 8 + g) * APAD + kb + tg];
                afH[mt][2] = AsH[(rB + g) * APAD + kb + 4 + tg];
                afH[mt][3] = AsH[(rB + 8 + g) * APAD + kb + 4 + tg];
                afL[mt][0] = AsL[(rB + g) * APAD + kb + tg];
                afL[mt][1] = AsL[(rB + 8 + g) * APAD + kb + tg];
                afL[mt][2] = AsL[(rB + g) * APAD + kb + 4 + tg];
                afL[mt][3] = AsL[(rB + 8 + g) * APAD + kb + 4 + tg];
            }
#pragma unroll
            for (int nt = 0; nt < 4; nt++) {
                int cc = wn * 32 + nt * 8 + g;
                unsigned bfH[2], bfL[2];
                bfH[0] = BsH[(kb + tg) * BPAD + cc];
                bfH[1] = BsH[(kb + 4 + tg) * BPAD + cc];
                bfL[0] = BsL[(kb + tg) * BPAD + cc];
                bfL[1] = BsL[(kb + 4 + tg) * BPAD + cc];
#pragma unroll
                for (int mt = 0; mt < 4; mt++) {
                    mma_bf16(acc[mt][nt], afH[mt], bfH);
                    mma_bf16(acc[mt][nt], afL[mt], bfH);
                    mma_bf16(acc[mt][nt], afH[mt], bfL);
                }
            }
        }
        __syncthreads();
        p ^= 1;
    }

    // -------- epilogue: store Y + fused per-CTA BN partial stats ------------
#pragma unroll
    for (int nt = 0; nt < 4; nt++) {
        float se = 0.f, so = 0.f, qe = 0.f, qo = 0.f;
#pragma unroll
        for (int mt = 0; mt < 4; mt++) {
            float c0 = acc[mt][nt][0], c1 = acc[mt][nt][1];
            float c2 = acc[mt][nt][2], c3 = acc[mt][nt][3];
            int r   = row0 + wm * 64 + mt * 16 + g;
            int col = wn * 32 + nt * 8 + tg * 2;
            *(float2*)(Y + (size_t)r * 128 + col)       = make_float2(c0, c1);
            *(float2*)(Y + (size_t)(r + 8) * 128 + col) = make_float2(c2, c3);
            se += c0 + c2;  so += c1 + c3;
            qe += c0 * c0 + c2 * c2;  qo += c1 * c1 + c3 * c3;
        }
#pragma unroll
        for (int o = 4; o < 32; o <<= 1) {
            se += __shfl_xor_sync(0xffffffffu, se, o);
            so += __shfl_xor_sync(0xffffffffu, so, o);
            qe += __shfl_xor_sync(0xffffffffu, qe, o);
            qo += __shfl_xor_sync(0xffffffffu, qo, o);
        }
        if (lane < 4) {
            int col = wn * 32 + nt * 8 + lane * 2;
            ssum[wm][col]     = se;  ssum[wm][col + 1] = so;
            ssq[wm][col]      = qe;  ssq[wm][col + 1]  = qo;
        }
    }
    __syncthreads();
    if (tid < 128) {
        int slot = ((zbase + z) * DCH + tid) * MBLK + blockIdx.x;
        g_psum[slot]   = ssum[0][tid] + ssum[1][tid];
        g_psumsq[slot] = ssq[0][tid] + ssq[1][tid];
    }
}

// ---------------- BN finalize v2: warp-per-channel, contiguous loads --------
__global__ void bn_finalize_kernel(const float* __restrict__ g0, const float* __restrict__ be0,
                                   const float* __restrict__ g1, const float* __restrict__ be1,
                                   const float* __restrict__ g2, const float* __restrict__ be2,
                                   int zbase)
{
    int z = blockIdx.x;
    const float* g  = (z == 0) ? g0 : (z == 1) ? g1 : g2;
    const float* be = (z == 0) ? be0 : (z == 1) ? be1 : be2;
    int wid  = threadIdx.x >> 5;
    int lane = threadIdx.x & 31;
    const float inv_cnt = 1.f / (float)ROWS;

#pragma unroll
    for (int i = 0; i < 8; i++) {
        int ch = wid * 8 + i;
        const float* ps = g_psum   + ((size_t)(zbase + z) * DCH + ch) * MBLK + lane * 12;
        const float* qs = g_psumsq + ((size_t)(zbase + z) * DCH + ch) * MBLK + lane * 12;
        float s = 0.f, s2 = 0.f;
#pragma unroll
        for (int j = 0; j < 3; j++) {
            float4 a = *(const float4*)(ps + j * 4);
            float4 b = *(const float4*)(qs + j * 4);
            s  += (a.x + a.y) + (a.z + a.w);
            s2 += (b.x + b.y) + (b.z + b.w);
        }
#pragma unroll
        for (int o = 16; o > 0; o >>= 1) {
            s  += __shfl_xor_sync(0xffffffffu, s, o);
            s2 += __shfl_xor_sync(0xffffffffu, s2, o);
        }
        if (lane == 0) {
            float mu  = s * inv_cnt;
            float var = s2 * inv_cnt - mu * mu;
            float sc  = g[ch] * rsqrtf(var + 1e-5f);
            g_scale[(zbase + z) * 128 + ch] = sc;
            g_shift[(zbase + z) * 128 + ch] = be[ch] - mu * sc;
        }
    }
}

// ---------------- attention inner-loop macros (pipelined) --------------------
#define QK_STRIP(Cd, n0_) do {                                               \
    _Pragma("unroll")                                                        \
    for (int nt = 0; nt < 4; nt++) {                                         \
        Cd[nt][0] = 0.f; Cd[nt][1] = 0.f; Cd[nt][2] = 0.f; Cd[nt][3] = 0.f;  \
    }                                                                        \
    _Pragma("unroll")                                                        \
    for (int ks = 0; ks < 4; ks++) {                                         \
        _Pragma("unroll")                                                    \
        for (int nt = 0; nt < 4; nt++) {                                     \
            int cc_ = (n0_) + nt * 8 + g;                                    \
            uint2 b2_ = *(const uint2*)&Ktp[(ks * 4 + tg) * KT2PAD + 2 * cc_]; \
            unsigned b_[2] = {b2_.x, b2_.y};                                 \
            mma_tf32(Cd[nt], aq[ks], b_);                                    \
        }                                                                    \
    }                                                                        \
} while (0)

#define SPV_STRIP(Cs, kv_) do {                                              \
    unsigned w0_ = __ldg(&g_mask[r0 * 16 + (kv_)]);                          \
    unsigned w1_ = __ldg(&g_mask[r1 * 16 + (kv_)]);                          \
    _Pragma("unroll")                                                        \
    for (int nt = 0; nt < 4; nt++) {                                         \
        int sh_ = nt * 8 + 2 * tg;                                           \
        Cs[nt][0] = ((w0_ >> sh_) & 1u)       ? ex2f(fmaf(Cs[nt][0], K1, K0)) : 0.f; \
        Cs[nt][1] = ((w0_ >> (sh_ + 1)) & 1u) ? ex2f(fmaf(Cs[nt][1], K1, K0)) : 0.f; \
        Cs[nt][2] = ((w1_ >> sh_) & 1u)       ? ex2f(fmaf(Cs[nt][2], K1, K0)) : 0.f; \
        Cs[nt][3] = ((w1_ >> (sh_ + 1)) & 1u) ? ex2f(fmaf(Cs[nt][3], K1, K0)) : 0.f; \
    }                                                                        \
    _Pragma("unroll")                                                        \
    for (int kt = 0; kt < 2; kt++) {                                         \
        unsigned ahi_[4], alo_[4];                                           \
        packsplit(Cs[2 * kt][0],     Cs[2 * kt][1],     ahi_[0], alo_[0]);   \
        packsplit(Cs[2 * kt][2],     Cs[2 * kt][3],     ahi_[1], alo_[1]);   \
        packsplit(Cs[2 * kt + 1][0], Cs[2 * kt + 1][1], ahi_[2], alo_[2]);   \
        packsplit(Cs[2 * kt + 1][2], Cs[2 * kt + 1][3], ahi_[3], alo_[3]);   \
        const int pblk_ = (kv_) * 2 + kt;                                    \
        _Pragma("unroll")                                                    \
        for (int nt = 0; nt < 4; nt++) {                                     \
            int bofs_ = (pblk_ * 4 + tg) * VPPAD + 2 * (nt * 8 + g);         \
            uint2 bh2_ = *(const uint2*)&Vh[bofs_];                          \
            uint2 bl2_ = *(const uint2*)&Vl[bofs_];                          \
            unsigned bh_[2] = {bh2_.x, bh2_.y};                              \
            unsigned bl_[2] = {bl2_.x, bl2_.y};                              \
            mma_bf16(o[nt], ahi_, bh_);                                      \
            mma_bf16(o[nt], alo_, bh_);                                      \
            mma_bf16(o[nt], ahi_, bl_);                                      \
        }                                                                    \
        mma_bf16(o5, ahi_, bones);                                           \
        mma_bf16(o5, alo_, bones);                                           \
    }                                                                        \
} while (0)

// ---------------- dense tensor-core masked flash-attention v8 ---------------
// QK tf32, PV split-bf16 (no transpose), ones-mma denominator, no-max
// softmax, LDG mask, 2-deep kv software pipeline. Epilogue writes float2
// (R12 o-path restored).
__global__ __launch_bounds__(512)
void attn_mma_kernel()
{
    extern __shared__ unsigned smu[];
    unsigned* Ktp = smu;                          // [16][KT2PAD]  K^T tf32 paired
    unsigned* Vh  = Ktp + 16 * KT2PAD;            // [128][VPPAD]  V hi bf16 paired
    unsigned* Vl  = Vh  + 128 * VPPAD;            // [128][VPPAD]  V lo bf16 paired
    unsigned* Asq = Vl  + 128 * VPPAD;            // [256][AQPAD]  Q tile tf32

    const int bt   = blockIdx.x;
    const int h    = blockIdx.y;
    const int tid  = threadIdx.x;
    const int lane = tid & 31;
    const int wid  = tid >> 5;                    // 0..15
    const int g    = lane >> 2;
    const int tg   = lane & 3;
    const size_t rowbase = (size_t)bt * NNODES;
    const int cb = h * 32;

    const float scq = g_scale[0 * 128 + cb + lane], shq = g_shift[0 * 128 + cb + lane];
    const float sck = g_scale[1 * 128 + cb + lane], shk = g_shift[1 * 128 + cb + lane];
    const float scv = g_scale[2 * 128 + cb + lane], shv = g_shift[2 * 128 + cb + lane];

    // stage K -> Ktp (tf32, channel-paired) and V -> Vh/Vl (bf16 split, paired)
    {
        const int c     = lane;
        const int krow  = (c >> 3) * 4 + (c & 3);
        const int khalf = (c & 7) >> 2;
        for (int idx = tid; idx < NNODES * 32; idx += 512) {
            int n = idx >> 5;                     // (idx & 31) == lane
            float kv = g_kraw[(rowbase + n) * 128 + cb + c];
            Ktp[krow * KT2PAD + 2 * n + khalf] =
                f2tf32(fmaxf(0.f, fmaf(kv, sck, shk)));
            float vv = g_vraw[(rowbase + n) * 128 + cb + c];
            float vfull = fmaxf(0.f, fmaf(vv, scv, shv));
            __nv_bfloat16 vhb = __float2bfloat16_rn(vfull);
            float vhf = __bfloat162float(vhb);
            __nv_bfloat16 vlb = __float2bfloat16_rn(vfull - vhf);
            int p = n >> 1, q = p & 7;
            int vofs = ((p >> 3) * 4 + (q & 3)) * VPPAD + 2 * c + (q >> 2);
            ((unsigned short*)&Vh[vofs])[n & 1] = *(unsigned short*)&vhb;
            ((unsigned short*)&Vl[vofs])[n & 1] = *(unsigned short*)&vlb;
        }
    }
    __syncthreads();

    const int q0 = wid * 16;
    const float K1 = 0.72134752044f;   // log2(e)/2
    const float K0 = -43.2808512267f;  // -30*log2(e)
    const unsigned BONES0 = 0x3F803F80u;   // bf16 1.0 pair
    unsigned bones[2] = {BONES0, BONES0};

    for (int qt = 0; qt < 2; qt++) {
        for (int idx = tid; idx < 256 * 32; idx += 512) {
            int r = idx >> 5;
            float qv = g_qraw[(rowbase + qt * 256 + r) * 128 + cb + lane];
            Asq[r * AQPAD + lane] = f2tf32(fmaxf(0.f, fmaf(qv, scq, shq)));
        }
        __syncthreads();

        const int r0 = qt * 256 + q0 + g;
        const int r1 = r0 + 8;

        // hoist Q fragments (invariant across kv strips)
        unsigned aq[4][4];
#pragma unroll
        for (int ks = 0; ks < 4; ks++) {
            const int kb = ks * 8;
            aq[ks][0] = Asq[(q0 + g) * AQPAD + kb + tg];
            aq[ks][1] = Asq[(q0 + g + 8) * AQPAD + kb + tg];
            aq[ks][2] = Asq[(q0 + g) * AQPAD + kb + tg + 4];
            aq[ks][3] = Asq[(q0 + g + 8) * AQPAD + kb + tg + 4];
        }

        float o[4][4], o5[4];
#pragma unroll
        for (int nt = 0; nt < 4; nt++)
#pragma unroll
            for (int q = 0; q < 4; q++) o[nt][q] = 0.f;
        o5[0] = 0.f; o5[1] = 0.f; o5[2] = 0.f; o5[3] = 0.f;

        // 2-deep pipelined kv loop: QK of next strip overlaps softmax/PV
        float cA[4][4], cB[4][4];
        QK_STRIP(cA, 0);
        for (int kv = 0; kv < 16; kv += 2) {
            QK_STRIP(cB, (kv + 1) * 32);
            SPV_STRIP(cA, kv);
            if (kv < 14) QK_STRIP(cA, (kv + 2) * 32);
            SPV_STRIP(cB, kv + 1);
        }

        // ---- epilogue: normalize, write ----
        float il0 = 1.f / o5[0], il1 = 1.f / o5[2];
#pragma unroll
        for (int nt = 0; nt < 4; nt++) {
            int col = cb + nt * 8 + 2 * tg;
            *(float2*)&g_aout[(rowbase + r0) * 128 + col] =
                make_float2(o[nt][0] * il0, o[nt][1] * il0);
            *(float2*)&g_aout[(rowbase + r1) * 128 + col] =
                make_float2(o[nt][2] * il1, o[nt][3] * il1);
        }
        __syncthreads();   // before next qt re-stages Asq
    }
}

// ---------------- final BN+ReLU into d_out (float4) --------------------------
__global__ void bn_apply_kernel(float* __restrict__ out)
{
    size_t i4 = (size_t)blockIdx.x * blockDim.x + threadIdx.x;
    if (i4 >= (size_t)ROWS * DCH / 4) return;
    int c0 = (int)((i4 * 4) & 127);
    float4 v = *(const float4*)&g_oraw[i4 * 4];
    float4 sc = *(const float4*)&g_scale[3 * 128 + c0];
    float4 sh = *(const float4*)&g_shift[3 * 128 + c0];
    float4 r;
    r.x = fmaxf(0.f, fmaf(v.x, sc.x, sh.x));
    r.y = fmaxf(0.f, fmaf(v.y, sc.y, sh.y));
    r.z = fmaxf(0.f, fmaf(v.z, sc.z, sh.z));
    r.w = fmaxf(0.f, fmaf(v.w, sc.w, sh.w));
    *(float4*)&out[i4 * 4] = r;
}

// =============================================================================
extern "C" void kernel_launch(void* const* d_in, const int* in_sizes, int n_in,
                              void* d_out, int out_size)
{
    (void)in_sizes; (void)n_in; (void)out_size;
    const float* X     = (const float*)d_in[0];
    const float* STE   = (const float*)d_in[1];
    const float* A     = (const float*)d_in[2];
    const float* Wq    = (const float*)d_in[3];
    const float* gq    = (const float*)d_in[5];
    const float* betaq = (const float*)d_in[6];
    const float* Wk    = (const float*)d_in[7];
    const float* gk    = (const float*)d_in[9];
    const float* betak = (const float*)d_in[10];
    const float* Wv    = (const float*)d_in[11];
    const float* gv    = (const float*)d_in[13];
    const float* betav = (const float*)d_in[14];
    const float* Wo    = (const float*)d_in[15];
    const float* go    = (const float*)d_in[17];
    const float* betao = (const float*)d_in[18];
    float* out = (float*)d_out;

    void *pq, *pk, *pv, *pa, *po;
    cudaGetSymbolAddress(&pq, g_qraw);
    cudaGetSymbolAddress(&pk, g_kraw);
    cudaGetSymbolAddress(&pv, g_vraw);
    cudaGetSymbolAddress(&pa, g_aout);
    cudaGetSymbolAddress(&po, g_oraw);

    const int smem_attn = (16 * KT2PAD + 2 * 128 * VPPAD + 256 * AQPAD)
                          * (int)sizeof(unsigned);   // ~172.5 KB
    cudaFuncSetAttribute(attn_mma_kernel, cudaFuncAttributeMaxDynamicSharedMemorySize,
                         smem_attn);
    cudaFuncSetAttribute(mma_gemm_kernel<256, true>,
                         cudaFuncAttributeMaxDynamicSharedMemorySize, GEMM_SMEM);
    cudaFuncSetAttribute(mma_gemm_kernel<128, false>,
                         cudaFuncAttributeMaxDynamicSharedMemorySize, GEMM_SMEM);

    // 1) setup: adjacency bitmap + weight pre-split (one launch)
    setup_kernel<<<16 + (WTOTAL + 1023) / 1024, 1024>>>(A, Wq, Wk, Wv, Wo);

    // 2) q/k/v projections (split-bf16 3-term, double-buffered, fused BN stats)
    mma_gemm_kernel<256, true><<<dim3(MBLK, 1, 3), 256, GEMM_SMEM>>>(
        X, STE, 0, 16384, (float*)pq, (float*)pk, (float*)pv, 0);

    // 3) BN finalize for q/k/v
    bn_finalize_kernel<<<3, 512>>>(gq, betaq, gk, betak, gv, betav, 0);

    // 4) dense tensor-core masked attention v8 (2-deep kv pipeline)
    attn_mma_kernel<<<dim3(NBT, NH), 512, smem_attn>>>();

    // 5) output projection (split-bf16 3-term, double-buffered, fused BN stats)
    mma_gemm_kernel<128, false><<<dim3(MBLK, 1, 1), 256, GEMM_SMEM>>>(
        (float*)pa, nullptr, WOFF_O, 0, (float*)po, (float*)po, (float*)po, 3);

    // 6) BN finalize for output
    bn_finalize_kernel<<<1, 512>>>(go, betao, go, betao, go, betao, 3);

    // 7) BN + ReLU -> d_out
    bn_apply_kernel<<<(ROWS * DCH / 4 + 255) / 256, 256>>>(out);
}

// round 16
// speedup vs baseline: 1.5748x; 1.5748x over previous
#include <cuda_runtime.h>
#include <cuda_bf16.h>
#include <math.h>

// Problem constants
#define ROWS   49152      // B*T*N = 8*12*512
#define DCH    128        // D
#define NNODES 512        // N
#define NBT    96         // B*T
#define NH     4          // heads (d)
#define MBLK   384        // ROWS / 128

// attention smem strides (units: 4B words)
#define KT2PAD 1032       // Ktp row stride: [16][1032], conflict-free LDS.64
#define VPPAD  72         // Vh/Vl row stride: [128][72], conflict-free LDS.64
#define AQPAD  36         // Asq row stride, [256][36]

// GEMM smem pads (bf16-pair words)
#define APAD 20           // A row stride in words (16 used)
#define BPAD 136          // B kpair stride in words

// pre-split W regions (pairword granularity)
#define WOFF_O 49152      // q:0, k:16384, v:32768, o:49152
#define WTOTAL 57344      // 3*16384 + 64*128

// ---------------- scratch (device globals; no cudaMalloc allowed) ----------
__device__ float    g_qraw[ROWS * DCH];
__device__ float    g_kraw[ROWS * DCH];
__device__ float    g_vraw[ROWS * DCH];
__device__ float    g_aout[ROWS * DCH];
__device__ float    g_oraw[ROWS * DCH];
__device__ unsigned g_mask[NNODES * 16];      // A>0 bitmap: row n, 16 words
__device__ unsigned g_WH[WTOTAL], g_WL[WTOTAL]; // pre-split packed bf16 weights
// deterministic BN partials, layout [z][ch][block]: slot=(z*128+ch)*384+b
__device__ float g_psum[4 * DCH * MBLK];
__device__ float g_psumsq[4 * DCH * MBLK];
__device__ float g_scale[4 * DCH];
__device__ float g_shift[4 * DCH];

// ---------------- helpers ----------------------------------------------------
__device__ __forceinline__ unsigned f2tf32(float f) {
    unsigned r;
    asm("cvt.rna.tf32.f32 %0, %1;" : "=r"(r) : "f"(f));
    return r;
}

__device__ __forceinline__ unsigned bf16x2pk(float hi, float lo) {
    unsigned r;
    asm("cvt.rn.bf16x2.f32 %0, %1, %2;" : "=r"(r) : "f"(hi), "f"(lo));
    return r;   // low 16 bits = bf16(lo), high = bf16(hi)
}

__device__ __forceinline__ float ex2f(float x) {
    float r;
    asm("ex2.approx.f32 %0, %1;" : "=f"(r) : "f"(x));
    return r;
}

// split packed pair (p0 even, p1 odd) into hi/lo packed words
__device__ __forceinline__ void packsplit(float p0, float p1,
                                          unsigned& hi, unsigned& lo) {
    hi = bf16x2pk(p1, p0);
    float f0 = __uint_as_float(hi << 16);
    float f1 = __uint_as_float(hi & 0xffff0000u);
    lo = bf16x2pk(p1 - f1, p0 - f0);
}

__device__ __forceinline__ void mma_tf32(float* c, const unsigned* a, const unsigned* b) {
    asm volatile(
        "mma.sync.aligned.m16n8k8.row.col.f32.tf32.tf32.f32 "
        "{%0,%1,%2,%3}, {%4,%5,%6,%7}, {%8,%9}, {%0,%1,%2,%3};\n"
        : "+f"(c[0]), "+f"(c[1]), "+f"(c[2]), "+f"(c[3])
        : "r"(a[0]), "r"(a[1]), "r"(a[2]), "r"(a[3]), "r"(b[0]), "r"(b[1]));
}

__device__ __forceinline__ void mma_bf16(float* c, const unsigned* a, const unsigned* b) {
    asm volatile(
        "mma.sync.aligned.m16n8k16.row.col.f32.bf16.bf16.f32 "
        "{%0,%1,%2,%3}, {%4,%5,%6,%7}, {%8,%9}, {%0,%1,%2,%3};\n"
        : "+f"(c[0]), "+f"(c[1]), "+f"(c[2]), "+f"(c[3])
        : "r"(a[0]), "r"(a[1]), "r"(a[2]), "r"(a[3]), "r"(b[0]), "r"(b[1]));
}

__device__ __forceinline__ void split_bf16(float v, unsigned short& h, unsigned short& l) {
    __nv_bfloat16 hb = __float2bfloat16_rn(v);
    float hf = __bfloat162float(hb);
    __nv_bfloat16 lb = __float2bfloat16_rn(v - hf);
    h = *(unsigned short*)&hb;
    l = *(unsigned short*)&lb;
}

__device__ __forceinline__ unsigned pack2(unsigned short lo, unsigned short hi) {
    return (unsigned)lo | ((unsigned)hi << 16);   // low 16 = even-k element
}

// ---------------- setup: adjacency bitmap + weight pre-split (merged) -------
__global__ void setup_kernel(const float* __restrict__ A,
                             const float* __restrict__ Wq,
                             const float* __restrict__ Wk,
                             const float* __restrict__ Wv,
                             const float* __restrict__ Wo)
{
    if (blockIdx.x < 16) {
        int row  = (blockIdx.x * 1024 + threadIdx.x) >> 5;
        int lane = threadIdx.x & 31;
        for (int w = 0; w < 16; w++) {
            float a = A[row * NNODES + w * 32 + lane];
            unsigned bal = __ballot_sync(0xffffffffu, a > 0.f);
            if (lane == 0) g_mask[row * 16 + w] = bal;
        }
    } else {
        int idx = (blockIdx.x - 16) * 1024 + threadIdx.x;
        if (idx >= WTOTAL) return;
        const float* W;
        int off;
        if (idx < 16384)      { W = Wq; off = 0; }
        else if (idx < 32768) { W = Wk; off = 16384; }
        else if (idx < 49152) { W = Wv; off = 32768; }
        else                  { W = Wo; off = WOFF_O; }
        int local = idx - off;
        int kp = local >> 7, n = local & 127;
        float v0 = W[(size_t)(2 * kp) * 128 + n];
        float v1 = W[(size_t)(2 * kp + 1) * 128 + n];
        unsigned short h0, l0, h1, l1;
        split_bf16(v0, h0, l0);
        split_bf16(v1, h1, l1);
        g_WH[idx] = pack2(h0, h1);
        g_WL[idx] = pack2(l0, l1);
    }
}

// ---------------- split-bf16 tensor GEMM, 128x128 tile, BK=32 ---------------
// R12-exact path: Y = A @ W via AhBh + AlBh + AhBl (~fp32 accuracy).
// Weights pre-split -> B staging is a plain LDG.128/STS copy; A split inline.
// Fused BN partials in [z][ch][block] layout.
template <int KDIM, bool CAT>
__global__ __launch_bounds__(256)
void mma_gemm_kernel(const float* __restrict__ A0, const float* __restrict__ A1,
                     int wbase, int wstep,
                     float* __restrict__ Y0, float* __restrict__ Y1,
                     float* __restrict__ Y2, int zbase)
{
    __shared__ __align__(16) unsigned AsH[128 * APAD], AsL[128 * APAD];
    __shared__ __align__(16) unsigned BsH[16 * BPAD],  BsL[16 * BPAD];
    __shared__ float ssum[2][128], ssq[2][128];

    const int z = blockIdx.z;
    float* Y = (z == 0) ? Y0 : (z == 1) ? Y1 : Y2;
    const unsigned* WH = g_WH + wbase + z * wstep;
    const unsigned* WL = g_WL + wbase + z * wstep;

    const int tid  = threadIdx.x;
    const int lane = tid & 31;
    const int wid  = tid >> 5;
    const int wm   = wid >> 2;
    const int wn   = wid & 3;
    const int row0 = blockIdx.x * 128;
    const int g    = lane >> 2;
    const int tg   = lane & 3;

    float acc[4][4][4];
#pragma unroll
    for (int mt = 0; mt < 4; mt++)
#pragma unroll
        for (int nt = 0; nt < 4; nt++)
#pragma unroll
            for (int q = 0; q < 4; q++) acc[mt][nt][q] = 0.f;

    for (int k0 = 0; k0 < KDIM; k0 += 32) {
        const int kp0 = k0 >> 1;

        // B tile: direct copy of pre-split pairwords
#pragma unroll
        for (int t = 0; t < 2; t++) {
            int i  = tid + 256 * t;
            int kp = i >> 5;
            int n4 = (i & 31) << 2;
            uint4 hv = *(const uint4*)&WH[(size_t)(kp0 + kp) * 128 + n4];
            uint4 lv = *(const uint4*)&WL[(size_t)(kp0 + kp) * 128 + n4];
            *(uint4*)&BsH[kp * BPAD + n4] = hv;
            *(uint4*)&BsL[kp * BPAD + n4] = lv;
        }

        // A tile: load + split inline
        {
            const float* Abase;
            int kofs;
            if (CAT) {
                if (k0 < 128) { Abase = A0; kofs = k0; }
                else          { Abase = A1; kofs = k0 - 128; }
            } else { Abase = A0; kofs = k0; }
#pragma unroll
            for (int t = 0; t < 4; t++) {
                int i  = tid + 256 * t;
                int r  = i >> 3;
                int kq = (i & 7) << 2;
                float4 v = *(const float4*)(Abase + (size_t)(row0 + r) * 128 + kofs + kq);
                unsigned short hx, lx, hy, ly, hz, lz, hw, lw;
                split_bf16(v.x, hx, lx); split_bf16(v.y, hy, ly);
                split_bf16(v.z, hz, lz); split_bf16(v.w, hw, lw);
                int o = r * APAD + (kq >> 1);
                AsH[o + 0] = pack2(hx, hy);  AsH[o + 1] = pack2(hz, hw);
                AsL[o + 0] = pack2(lx, ly);  AsL[o + 1] = pack2(lz, lw);
            }
        }
        __syncthreads();

#pragma unroll
        for (int s = 0; s < 2; s++) {
            const int kb = s * 8;
            unsigned afH[4][4], afL[4][4];
#pragma unroll
            for (int mt = 0; mt < 4; mt++) {
                int rB = wm * 64 + mt * 16;
                afH[mt][0] = AsH[(rB + g) * APAD + kb + tg];
                afH[mt][1] = AsH[(rB + 8 + g) * APAD + kb + tg];
                afH[mt][2] = AsH[(rB + g) * APAD + kb + 4 + tg];
                afH[mt][3] = AsH[(rB + 8 + g) * APAD + kb + 4 + tg];
                afL[mt][0] = AsL[(rB + g) * APAD + kb + tg];
                afL[mt][1] = AsL[(rB + 8 + g) * APAD + kb + tg];
                afL[mt][2] = AsL[(rB + g) * APAD + kb + 4 + tg];
                afL[mt][3] = AsL[(rB + 8 + g) * APAD + kb + 4 + tg];
            }
#pragma unroll
            for (int nt = 0; nt < 4; nt++) {
                int cc = wn * 32 + nt * 8 + g;
                unsigned bfH[2], bfL[2];
                bfH[0] = BsH[(kb + tg) * BPAD + cc];
                bfH[1] = BsH[(kb + 4 + tg) * BPAD + cc];
                bfL[0] = BsL[(kb + tg) * BPAD + cc];
                bfL[1] = BsL[(kb + 4 + tg) * BPAD + cc];
#pragma unroll
                for (int mt = 0; mt < 4; mt++) {
                    mma_bf16(acc[mt][nt], afH[mt], bfH);
                    mma_bf16(acc[mt][nt], afL[mt], bfH);
                    mma_bf16(acc[mt][nt], afH[mt], bfL);
                }
            }
        }
        __syncthreads();
    }

    // -------- epilogue: store Y + fused per-CTA BN partial stats ------------
#pragma unroll
    for (int nt = 0; nt < 4; nt++) {
        float se = 0.f, so = 0.f, qe = 0.f, qo = 0.f;
#pragma unroll
        for (int mt = 0; mt < 4; mt++) {
            float c0 = acc[mt][nt][0], c1 = acc[mt][nt][1];
            float c2 = acc[mt][nt][2], c3 = acc[mt][nt][3];
            int r   = row0 + wm * 64 + mt * 16 + g;
            int col = wn * 32 + nt * 8 + tg * 2;
            *(float2*)(Y + (size_t)r * 128 + col)       = make_float2(c0, c1);
            *(float2*)(Y + (size_t)(r + 8) * 128 + col) = make_float2(c2, c3);
            se += c0 + c2;  so += c1 + c3;
            qe += c0 * c0 + c2 * c2;  qo += c1 * c1 + c3 * c3;
        }
#pragma unroll
        for (int o = 4; o < 32; o <<= 1) {
            se += __shfl_xor_sync(0xffffffffu, se, o);
            so += __shfl_xor_sync(0xffffffffu, so, o);
            qe += __shfl_xor_sync(0xffffffffu, qe, o);
            qo += __shfl_xor_sync(0xffffffffu, qo, o);
        }
        if (lane < 4) {
            int col = wn * 32 + nt * 8 + lane * 2;
            ssum[wm][col]     = se;  ssum[wm][col + 1] = so;
            ssq[wm][col]      = qe;  ssq[wm][col + 1]  = qo;
        }
    }
    __syncthreads();
    if (tid < 128) {
        int slot = ((zbase + z) * DCH + tid) * MBLK + blockIdx.x;
        g_psum[slot]   = ssum[0][tid] + ssum[1][tid];
        g_psumsq[slot] = ssq[0][tid] + ssq[1][tid];
    }
}

// ---------------- BN finalize v2: warp-per-channel, contiguous loads --------
__global__ void bn_finalize_kernel(const float* __restrict__ g0, const float* __restrict__ be0,
                                   const float* __restrict__ g1, const float* __restrict__ be1,
                                   const float* __restrict__ g2, const float* __restrict__ be2,
                                   int zbase)
{
    int z = blockIdx.x;
    const float* g  = (z == 0) ? g0 : (z == 1) ? g1 : g2;
    const float* be = (z == 0) ? be0 : (z == 1) ? be1 : be2;
    int wid  = threadIdx.x >> 5;
    int lane = threadIdx.x & 31;
    const float inv_cnt = 1.f / (float)ROWS;

#pragma unroll
    for (int i = 0; i < 8; i++) {
        int ch = wid * 8 + i;
        const float* ps = g_psum   + ((size_t)(zbase + z) * DCH + ch) * MBLK + lane * 12;
        const float* qs = g_psumsq + ((size_t)(zbase + z) * DCH + ch) * MBLK + lane * 12;
        float s = 0.f, s2 = 0.f;
#pragma unroll
        for (int j = 0; j < 3; j++) {
            float4 a = *(const float4*)(ps + j * 4);
            float4 b = *(const float4*)(qs + j * 4);
            s  += (a.x + a.y) + (a.z + a.w);
            s2 += (b.x + b.y) + (b.z + b.w);
        }
#pragma unroll
        for (int o = 16; o > 0; o >>= 1) {
            s  += __shfl_xor_sync(0xffffffffu, s, o);
            s2 += __shfl_xor_sync(0xffffffffu, s2, o);
        }
        if (lane == 0) {
            float mu  = s * inv_cnt;
            float var = s2 * inv_cnt - mu * mu;
            float sc  = g[ch] * rsqrtf(var + 1e-5f);
            g_scale[(zbase + z) * 128 + ch] = sc;
            g_shift[(zbase + z) * 128 + ch] = be[ch] - mu * sc;
        }
    }
}

// ---------------- attention inner-loop macros (pipelined) --------------------
#define QK_STRIP(Cd, n0_) do {                                               \
    _Pragma("unroll")                                                        \
    for (int nt = 0; nt < 4; nt++) {                                         \
        Cd[nt][0] = 0.f; Cd[nt][1] = 0.f; Cd[nt][2] = 0.f; Cd[nt][3] = 0.f;  \
    }                                                                        \
    _Pragma("unroll")                                                        \
    for (int ks = 0; ks < 4; ks++) {                                         \
        _Pragma("unroll")                                                    \
        for (int nt = 0; nt < 4; nt++) {                                     \
            int cc_ = (n0_) + nt * 8 + g;                                    \
            uint2 b2_ = *(const uint2*)&Ktp[(ks * 4 + tg) * KT2PAD + 2 * cc_]; \
            unsigned b_[2] = {b2_.x, b2_.y};                                 \
            mma_tf32(Cd[nt], aq[ks], b_);                                    \
        }                                                                    \
    }                                                                        \
} while (0)

#define SPV_STRIP(Cs, kv_) do {                                              \
    unsigned w0_ = __ldg(&g_mask[r0 * 16 + (kv_)]);                          \
    unsigned w1_ = __ldg(&g_mask[r1 * 16 + (kv_)]);                          \
    _Pragma("unroll")                                                        \
    for (int nt = 0; nt < 4; nt++) {                                         \
        int sh_ = nt * 8 + 2 * tg;                                           \
        Cs[nt][0] = ((w0_ >> sh_) & 1u)       ? ex2f(fmaf(Cs[nt][0], K1, K0)) : 0.f; \
        Cs[nt][1] = ((w0_ >> (sh_ + 1)) & 1u) ? ex2f(fmaf(Cs[nt][1], K1, K0)) : 0.f; \
        Cs[nt][2] = ((w1_ >> sh_) & 1u)       ? ex2f(fmaf(Cs[nt][2], K1, K0)) : 0.f; \
        Cs[nt][3] = ((w1_ >> (sh_ + 1)) & 1u) ? ex2f(fmaf(Cs[nt][3], K1, K0)) : 0.f; \
    }                                                                        \
    _Pragma("unroll")                                                        \
    for (int kt = 0; kt < 2; kt++) {                                         \
        unsigned ahi_[4], alo_[4];                                           \
        packsplit(Cs[2 * kt][0],     Cs[2 * kt][1],     ahi_[0], alo_[0]);   \
        packsplit(Cs[2 * kt][2],     Cs[2 * kt][3],     ahi_[1], alo_[1]);   \
        packsplit(Cs[2 * kt + 1][0], Cs[2 * kt + 1][1], ahi_[2], alo_[2]);   \
        packsplit(Cs[2 * kt + 1][2], Cs[2 * kt + 1][3], ahi_[3], alo_[3]);   \
        const int pblk_ = (kv_) * 2 + kt;                                    \
        _Pragma("unroll")                                                    \
        for (int nt = 0; nt < 4; nt++) {                                     \
            int bofs_ = (pblk_ * 4 + tg) * VPPAD + 2 * (nt * 8 + g);         \
            uint2 bh2_ = *(const uint2*)&Vh[bofs_];                          \
            uint2 bl2_ = *(const uint2*)&Vl[bofs_];                          \
            unsigned bh_[2] = {bh2_.x, bh2_.y};                              \
            unsigned bl_[2] = {bl2_.x, bl2_.y};                              \
            mma_bf16(o[nt], ahi_, bh_);                                      \
            mma_bf16(o[nt], alo_, bh_);                                      \
            mma_bf16(o[nt], ahi_, bl_);                                      \
        }                                                                    \
        mma_bf16(o5, ahi_, bones);                                           \
        mma_bf16(o5, alo_, bones);                                           \
    }                                                                        \
} while (0)

// ---------------- dense tensor-core masked flash-attention v8 ---------------
// QK tf32, PV split-bf16 (no transpose), ones-mma denominator, no-max
// softmax, LDG mask, 2-deep kv software pipeline, float2 epilogue.
__global__ __launch_bounds__(512)
void attn_mma_kernel()
{
    extern __shared__ unsigned smu[];
    unsigned* Ktp = smu;                          // [16][KT2PAD]  K^T tf32 paired
    unsigned* Vh  = Ktp + 16 * KT2PAD;            // [128][VPPAD]  V hi bf16 paired
    unsigned* Vl  = Vh  + 128 * VPPAD;            // [128][VPPAD]  V lo bf16 paired
    unsigned* Asq = Vl  + 128 * VPPAD;            // [256][AQPAD]  Q tile tf32

    const int bt   = blockIdx.x;
    const int h    = blockIdx.y;
    const int tid  = threadIdx.x;
    const int lane = tid & 31;
    const int wid  = tid >> 5;                    // 0..15
    const int g    = lane >> 2;
    const int tg   = lane & 3;
    const size_t rowbase = (size_t)bt * NNODES;
    const int cb = h * 32;

    const float scq = g_scale[0 * 128 + cb + lane], shq = g_shift[0 * 128 + cb + lane];
    const float sck = g_scale[1 * 128 + cb + lane], shk = g_shift[1 * 128 + cb + lane];
    const float scv = g_scale[2 * 128 + cb + lane], shv = g_shift[2 * 128 + cb + lane];

    // stage K -> Ktp (tf32, channel-paired) and V -> Vh/Vl (bf16 split, paired)
    {
        const int c     = lane;
        const int krow  = (c >> 3) * 4 + (c & 3);
        const int khalf = (c & 7) >> 2;
        for (int idx = tid; idx < NNODES * 32; idx += 512) {
            int n = idx >> 5;                     // (idx & 31) == lane
            float kv = g_kraw[(rowbase + n) * 128 + cb + c];
            Ktp[krow * KT2PAD + 2 * n + khalf] =
                f2tf32(fmaxf(0.f, fmaf(kv, sck, shk)));
            float vv = g_vraw[(rowbase + n) * 128 + cb + c];
            float vfull = fmaxf(0.f, fmaf(vv, scv, shv));
            __nv_bfloat16 vhb = __float2bfloat16_rn(vfull);
            float vhf = __bfloat162float(vhb);
            __nv_bfloat16 vlb = __float2bfloat16_rn(vfull - vhf);
            int p = n >> 1, q = p & 7;
            int vofs = ((p >> 3) * 4 + (q & 3)) * VPPAD + 2 * c + (q >> 2);
            ((unsigned short*)&Vh[vofs])[n & 1] = *(unsigned short*)&vhb;
            ((unsigned short*)&Vl[vofs])[n & 1] = *(unsigned short*)&vlb;
        }
    }
    __syncthreads();

    const int q0 = wid * 16;
    const float K1 = 0.72134752044f;   // log2(e)/2
    const float K0 = -43.2808512267f;  // -30*log2(e)
    const unsigned BONES0 = 0x3F803F80u;   // bf16 1.0 pair
    unsigned bones[2] = {BONES0, BONES0};

    for (int qt = 0; qt < 2; qt++) {
        for (int idx = tid; idx < 256 * 32; idx += 512) {
            int r = idx >> 5;
            float qv = g_qraw[(rowbase + qt * 256 + r) * 128 + cb + lane];
            Asq[r * AQPAD + lane] = f2tf32(fmaxf(0.f, fmaf(qv, scq, shq)));
        }
        __syncthreads();

        const int r0 = qt * 256 + q0 + g;
        const int r1 = r0 + 8;

        // hoist Q fragments (invariant across kv strips)
        unsigned aq[4][4];
#pragma unroll
        for (int ks = 0; ks < 4; ks++) {
            const int kb = ks * 8;
            aq[ks][0] = Asq[(q0 + g) * AQPAD + kb + tg];
            aq[ks][1] = Asq[(q0 + g + 8) * AQPAD + kb + tg];
            aq[ks][2] = Asq[(q0 + g) * AQPAD + kb + tg + 4];
            aq[ks][3] = Asq[(q0 + g + 8) * AQPAD + kb + tg + 4];
        }

        float o[4][4], o5[4];
#pragma unroll
        for (int nt = 0; nt < 4; nt++)
#pragma unroll
            for (int q = 0; q < 4; q++) o[nt][q] = 0.f;
        o5[0] = 0.f; o5[1] = 0.f; o5[2] = 0.f; o5[3] = 0.f;

        // 2-deep pipelined kv loop: QK of next strip overlaps softmax/PV
        float cA[4][4], cB[4][4];
        QK_STRIP(cA, 0);
        for (int kv = 0; kv < 16; kv += 2) {
            QK_STRIP(cB, (kv + 1) * 32);
            SPV_STRIP(cA, kv);
            if (kv < 14) QK_STRIP(cA, (kv + 2) * 32);
            SPV_STRIP(cB, kv + 1);
        }

        // ---- epilogue: normalize, write ----
        float il0 = 1.f / o5[0], il1 = 1.f / o5[2];
#pragma unroll
        for (int nt = 0; nt < 4; nt++) {
            int col = cb + nt * 8 + 2 * tg;
            *(float2*)&g_aout[(rowbase + r0) * 128 + col] =
                make_float2(o[nt][0] * il0, o[nt][1] * il0);
            *(float2*)&g_aout[(rowbase + r1) * 128 + col] =
                make_float2(o[nt][2] * il1, o[nt][3] * il1);
        }
        __syncthreads();   // before next qt re-stages Asq
    }
}

// ---------------- final BN+ReLU into d_out (float4) --------------------------
__global__ void bn_apply_kernel(float* __restrict__ out)
{
    size_t i4 = (size_t)blockIdx.x * blockDim.x + threadIdx.x;
    if (i4 >= (size_t)ROWS * DCH / 4) return;
    int c0 = (int)((i4 * 4) & 127);
    float4 v = *(const float4*)&g_oraw[i4 * 4];
    float4 sc = *(const float4*)&g_scale[3 * 128 + c0];
    float4 sh = *(const float4*)&g_shift[3 * 128 + c0];
    float4 r;
    r.x = fmaxf(0.f, fmaf(v.x, sc.x, sh.x));
    r.y = fmaxf(0.f, fmaf(v.y, sc.y, sh.y));
    r.z = fmaxf(0.f, fmaf(v.z, sc.z, sh.z));
    r.w = fmaxf(0.f, fmaf(v.w, sc.w, sh.w));
    *(float4*)&out[i4 * 4] = r;
}

// =============================================================================
extern "C" void kernel_launch(void* const* d_in, const int* in_sizes, int n_in,
                              void* d_out, int out_size)
{
    (void)in_sizes; (void)n_in; (void)out_size;
    const float* X     = (const float*)d_in[0];
    const float* STE   = (const float*)d_in[1];
    const float* A     = (const float*)d_in[2];
    const float* Wq    = (const float*)d_in[3];
    const float* gq    = (const float*)d_in[5];
    const float* betaq = (const float*)d_in[6];
    const float* Wk    = (const float*)d_in[7];
    const float* gk    = (const float*)d_in[9];
    const float* betak = (const float*)d_in[10];
    const float* Wv    = (const float*)d_in[11];
    const float* gv    = (const float*)d_in[13];
    const float* betav = (const float*)d_in[14];
    const float* Wo    = (const float*)d_in[15];
    const float* go    = (const float*)d_in[17];
    const float* betao = (const float*)d_in[18];
    float* out = (float*)d_out;

    void *pq, *pk, *pv, *pa, *po;
    cudaGetSymbolAddress(&pq, g_qraw);
    cudaGetSymbolAddress(&pk, g_kraw);
    cudaGetSymbolAddress(&pv, g_vraw);
    cudaGetSymbolAddress(&pa, g_aout);
    cudaGetSymbolAddress(&po, g_oraw);

    const int smem_attn = (16 * KT2PAD + 2 * 128 * VPPAD + 256 * AQPAD)
                          * (int)sizeof(unsigned);   // ~172.5 KB
    cudaFuncSetAttribute(attn_mma_kernel, cudaFuncAttributeMaxDynamicSharedMemorySize,
                         smem_attn);

    // 1) setup: adjacency bitmap + weight pre-split (one launch)
    setup_kernel<<<16 + (WTOTAL + 1023) / 1024, 1024>>>(A, Wq, Wk, Wv, Wo);

    // 2) q/k/v projections (split-bf16 3-term, R12 staging, fused BN stats)
    mma_gemm_kernel<256, true><<<dim3(MBLK, 1, 3), 256>>>(
        X, STE, 0, 16384, (float*)pq, (float*)pk, (float*)pv, 0);

    // 3) BN finalize for q/k/v
    bn_finalize_kernel<<<3, 512>>>(gq, betaq, gk, betak, gv, betav, 0);

    // 4) dense tensor-core masked attention v8 (2-deep kv pipeline)
    attn_mma_kernel<<<dim3(NBT, NH), 512, smem_attn>>>();

    // 5) output projection (split-bf16 3-term, R12 staging, fused BN stats)
    mma_gemm_kernel<128, false><<<dim3(MBLK, 1, 1), 256>>>(
        (float*)pa, nullptr, WOFF_O, 0, (float*)po, (float*)po, (float*)po, 3);

    // 6) BN finalize for output
    bn_finalize_kernel<<<1, 512>>>(go, betao, go, betao, go, betao, 3);

    // 7) BN + ReLU -> d_out
    bn_apply_kernel<<<(ROWS * DCH / 4 + 255) / 256, 256>>>(out);
}